// round 1
// baseline (speedup 1.0000x reference)
#include <cuda_runtime.h>
#include <math.h>

#define N_NODES 20000
#define N_EDGES 320000
#define NE_TOT  (N_EDGES + N_NODES)   /* 340000 incl self loops */
#define IN_CH   512
#define HID     128
#define HEADS   4
#define OUT_CH  256
#define L1_F    (HEADS * HID)         /* 512 */

#define A1_OFF  (N_NODES * OUT_CH)            /* 5,120,000 */
#define A2_OFF  (A1_OFF + NE_TOT * HEADS)     /* 6,480,000 */

/* ------------------------- scratch (device globals) ------------------------- */
__device__ float    g_h1[(size_t)N_NODES * L1_F];
__device__ float    g_agg1[(size_t)N_NODES * L1_F];
__device__ float    g_h2[(size_t)N_NODES * OUT_CH];
__device__ float    g_as1[N_NODES * HEADS];
__device__ float    g_ad1[N_NODES * HEADS];
__device__ float    g_as2[N_NODES];
__device__ float    g_ad2[N_NODES];
__device__ float    g_e1[NE_TOT * HEADS];
__device__ float    g_ex1[NE_TOT * HEADS];
__device__ float    g_e2[NE_TOT];
__device__ float    g_ex2[NE_TOT];
__device__ float    g_den1[N_NODES * HEADS];
__device__ unsigned g_max1[N_NODES * HEADS];
__device__ float    g_den2[N_NODES];
__device__ unsigned g_max2[N_NODES];

/* ------------------------- helpers ------------------------- */
__device__ __forceinline__ unsigned f2ord(float f) {
    unsigned u = __float_as_uint(f);
    return (u & 0x80000000u) ? ~u : (u | 0x80000000u);
}
__device__ __forceinline__ float ord2f(unsigned u) {
    return (u & 0x80000000u) ? __uint_as_float(u ^ 0x80000000u)
                             : __uint_as_float(~u);
}

__device__ __forceinline__ unsigned long long pack2(float lo, float hi) {
    unsigned long long d;
    asm("mov.b64 %0, {%1, %2};" : "=l"(d) : "f"(lo), "f"(hi));
    return d;
}
__device__ __forceinline__ void unpack2(float& lo, float& hi, unsigned long long v) {
    asm("mov.b64 {%0, %1}, %2;" : "=f"(lo), "=f"(hi) : "l"(v));
}
__device__ __forceinline__ unsigned long long fma2(unsigned long long a,
                                                   unsigned long long b,
                                                   unsigned long long c) {
    unsigned long long d;
    asm("fma.rn.f32x2 %0, %1, %2, %3;" : "=l"(d) : "l"(a), "l"(b), "l"(c));
    return d;
}

/* ------------------------- init ------------------------- */
__global__ void init_kernel(float* __restrict__ out, const float* __restrict__ b2) {
    int i = blockIdx.x * blockDim.x + threadIdx.x;
    if (i < N_NODES * L1_F)  g_agg1[i] = 0.f;
    if (i < N_NODES * HEADS) { g_den1[i] = 0.f; g_max1[i] = 0u; }
    if (i < N_NODES)         { g_den2[i] = 0.f; g_max2[i] = 0u; }
    if (i < N_NODES * OUT_CH) out[i] = b2[i & (OUT_CH - 1)];
}

/* ------------------------- SGEMM (fp32, f32x2 FMA) -------------------------
   C[M,N] = A[M,K] * B[K,N], row-major. N%128==0, K%16==0, M guarded. */
#define BM 128
#define BN 128
#define BK 16
#define APAD 132

__global__ __launch_bounds__(256)
void sgemm(const float* __restrict__ A, const float* __restrict__ B,
           float* __restrict__ C, int M, int N, int K) {
    __shared__ float As[BK][APAD];
    __shared__ float Bs[BK][BN];

    int m0 = blockIdx.y * BM;
    int n0 = blockIdx.x * BN;
    int tid = threadIdx.x;
    int tx = tid & 15, ty = tid >> 4;

    unsigned long long acc[8][4];
#pragma unroll
    for (int i = 0; i < 8; i++)
#pragma unroll
        for (int j = 0; j < 4; j++) acc[i][j] = 0ull;

    for (int k0 = 0; k0 < K; k0 += BK) {
#pragma unroll
        for (int l = 0; l < 2; l++) {
            int f = tid + 256 * l;
            int ar = f >> 2, ac4 = f & 3;
            float4 v = make_float4(0.f, 0.f, 0.f, 0.f);
            if (m0 + ar < M)
                v = *(const float4*)(A + (size_t)(m0 + ar) * K + k0 + ac4 * 4);
            As[ac4 * 4 + 0][ar] = v.x;
            As[ac4 * 4 + 1][ar] = v.y;
            As[ac4 * 4 + 2][ar] = v.z;
            As[ac4 * 4 + 3][ar] = v.w;
        }
#pragma unroll
        for (int l = 0; l < 2; l++) {
            int f = tid + 256 * l;
            int br = f >> 5, bc4 = f & 31;
            float4 v = *(const float4*)(B + (size_t)(k0 + br) * N + n0 + bc4 * 4);
            *(float4*)&Bs[br][bc4 * 4] = v;
        }
        __syncthreads();

#pragma unroll
        for (int k = 0; k < BK; k++) {
            float4 a0 = *(const float4*)&As[k][ty * 8];
            float4 a1 = *(const float4*)&As[k][ty * 8 + 4];
            float4 b0 = *(const float4*)&Bs[k][tx * 8];
            float4 b1 = *(const float4*)&Bs[k][tx * 8 + 4];
            unsigned long long bp[4] = { pack2(b0.x, b0.y), pack2(b0.z, b0.w),
                                         pack2(b1.x, b1.y), pack2(b1.z, b1.w) };
            float av[8] = { a0.x, a0.y, a0.z, a0.w, a1.x, a1.y, a1.z, a1.w };
#pragma unroll
            for (int i = 0; i < 8; i++) {
                unsigned long long ap = pack2(av[i], av[i]);
#pragma unroll
                for (int j = 0; j < 4; j++) acc[i][j] = fma2(ap, bp[j], acc[i][j]);
            }
        }
        __syncthreads();
    }

#pragma unroll
    for (int i = 0; i < 8; i++) {
        int m = m0 + ty * 8 + i;
        if (m < M) {
            float o[8];
#pragma unroll
            for (int j = 0; j < 4; j++) unpack2(o[2 * j], o[2 * j + 1], acc[i][j]);
            float* cp = C + (size_t)m * N + n0 + tx * 8;
            *(float4*)cp       = make_float4(o[0], o[1], o[2], o[3]);
            *(float4*)(cp + 4) = make_float4(o[4], o[5], o[6], o[7]);
        }
    }
}

/* ------------------------- attention coefficients -------------------------
   warp per (node, head): as[n,h] = <h[n,h,:], a_src[h,:]>, same for dst. */
template <int H, int C>
__global__ void attn_coef(const float* __restrict__ h,
                          const float* __restrict__ a_src,
                          const float* __restrict__ a_dst,
                          float* __restrict__ as, float* __restrict__ ad) {
    int gw = (blockIdx.x * blockDim.x + threadIdx.x) >> 5;
    int lane = threadIdx.x & 31;
    if (gw >= N_NODES * H) return;
    int n = gw / H, hh = gw % H;
    const float* hp = h + (size_t)n * (H * C) + hh * C;
    const float* sp = a_src + hh * C;
    const float* dp = a_dst + hh * C;
    float s = 0.f, d = 0.f;
#pragma unroll
    for (int c = lane; c < C; c += 32) {
        float v = hp[c];
        s += v * sp[c];
        d += v * dp[c];
    }
#pragma unroll
    for (int o = 16; o; o >>= 1) {
        s += __shfl_xor_sync(0xFFFFFFFFu, s, o);
        d += __shfl_xor_sync(0xFFFFFFFFu, d, o);
    }
    if (lane == 0) { as[gw] = s; ad[gw] = d; }
}

/* ------------------------- edge passes ------------------------- */
__device__ __forceinline__ void edge_nodes(const int* __restrict__ ei, int e,
                                           int& src, int& dst) {
    if (e < N_EDGES) { src = ei[e]; dst = ei[N_EDGES + e]; }
    else             { src = dst = e - N_EDGES; }
}

template <int H>
__global__ void edge_pass_a(const int* __restrict__ ei,
                            const float* __restrict__ as,
                            const float* __restrict__ ad,
                            float* __restrict__ e_out,
                            unsigned* __restrict__ emax) {
    int t = blockIdx.x * blockDim.x + threadIdx.x;
    if (t >= NE_TOT * H) return;
    int e = t / H, hh = t % H;
    int src, dst;
    edge_nodes(ei, e, src, dst);
    float v = as[src * H + hh] + ad[dst * H + hh];
    v = v > 0.f ? v : 0.2f * v;                 /* LeakyReLU(0.2) */
    e_out[t] = v;
    atomicMax(&emax[dst * H + hh], f2ord(v));
}

template <int H>
__global__ void edge_pass_b(const int* __restrict__ ei,
                            const float* __restrict__ e_in,
                            const unsigned* __restrict__ emax,
                            float* __restrict__ ex,
                            float* __restrict__ denom) {
    int t = blockIdx.x * blockDim.x + threadIdx.x;
    if (t >= NE_TOT * H) return;
    int e = t / H, hh = t % H;
    int src, dst;
    edge_nodes(ei, e, src, dst);
    float m = ord2f(emax[dst * H + hh]);
    float v = __expf(e_in[t] - m);
    ex[t] = v;
    atomicAdd(&denom[dst * H + hh], v);
}

/* warp per (edge, head): alpha, then agg[dst,h,:] += alpha * h[src,h,:]  */
template <int H, int C>
__global__ void aggregate(const int* __restrict__ ei,
                          const float* __restrict__ hfeat,
                          const float* __restrict__ ex,
                          const float* __restrict__ denom,
                          float* __restrict__ alpha_out,
                          float* __restrict__ agg) {
    int gw = (blockIdx.x * blockDim.x + threadIdx.x) >> 5;
    int lane = threadIdx.x & 31;
    if (gw >= NE_TOT * H) return;
    int e = gw / H, hh = gw % H;
    int src, dst;
    edge_nodes(ei, e, src, dst);
    float a = ex[gw] / denom[dst * H + hh];
    if (lane == 0) alpha_out[gw] = a;
    const float4* hp = (const float4*)(hfeat + (size_t)src * (H * C) + hh * C);
    float* op = agg + (size_t)dst * (H * C) + hh * C;
    constexpr int R = C / 128;
#pragma unroll
    for (int r = 0; r < R; r++) {
        float4 v = hp[lane + 32 * r];
        int base = (lane + 32 * r) * 4;
        atomicAdd(op + base + 0, a * v.x);
        atomicAdd(op + base + 1, a * v.y);
        atomicAdd(op + base + 2, a * v.z);
        atomicAdd(op + base + 3, a * v.w);
    }
}

/* ------------------------- bias + ELU on layer-1 output ------------------------- */
__global__ void elu_bias(const float* __restrict__ b1) {
    int i = blockIdx.x * blockDim.x + threadIdx.x;
    if (i >= N_NODES * L1_F) return;
    float v = g_agg1[i] + b1[i & (L1_F - 1)];
    g_agg1[i] = v > 0.f ? v : expm1f(v);
}

/* ------------------------- launch ------------------------- */
extern "C" void kernel_launch(void* const* d_in, const int* in_sizes, int n_in,
                              void* d_out, int out_size) {
    const float* x      = (const float*)d_in[0];
    const int*   ei     = (const int*)  d_in[1];
    const float* W1     = (const float*)d_in[2];
    const float* a_src1 = (const float*)d_in[3];
    const float* a_dst1 = (const float*)d_in[4];
    const float* b1     = (const float*)d_in[5];
    const float* W2     = (const float*)d_in[6];
    const float* a_src2 = (const float*)d_in[7];
    const float* a_dst2 = (const float*)d_in[8];
    const float* b2     = (const float*)d_in[9];
    float* out = (float*)d_out;

    float *h1, *agg1, *h2, *as1, *ad1, *as2, *ad2, *e1, *ex1, *e2, *ex2, *den1, *den2;
    unsigned *mx1, *mx2;
    cudaGetSymbolAddress((void**)&h1,   g_h1);
    cudaGetSymbolAddress((void**)&agg1, g_agg1);
    cudaGetSymbolAddress((void**)&h2,   g_h2);
    cudaGetSymbolAddress((void**)&as1,  g_as1);
    cudaGetSymbolAddress((void**)&ad1,  g_ad1);
    cudaGetSymbolAddress((void**)&as2,  g_as2);
    cudaGetSymbolAddress((void**)&ad2,  g_ad2);
    cudaGetSymbolAddress((void**)&e1,   g_e1);
    cudaGetSymbolAddress((void**)&ex1,  g_ex1);
    cudaGetSymbolAddress((void**)&e2,   g_e2);
    cudaGetSymbolAddress((void**)&ex2,  g_ex2);
    cudaGetSymbolAddress((void**)&den1, g_den1);
    cudaGetSymbolAddress((void**)&den2, g_den2);
    cudaGetSymbolAddress((void**)&mx1,  g_max1);
    cudaGetSymbolAddress((void**)&mx2,  g_max2);

    /* init scratch + bias-broadcast output */
    init_kernel<<<(N_NODES * L1_F + 255) / 256, 256>>>(out, b2);

    /* layer 1 */
    sgemm<<<dim3(L1_F / BN, (N_NODES + BM - 1) / BM), 256>>>(x, W1, h1, N_NODES, L1_F, IN_CH);
    attn_coef<HEADS, HID><<<(N_NODES * HEADS + 7) / 8, 256>>>(h1, a_src1, a_dst1, as1, ad1);
    edge_pass_a<HEADS><<<(NE_TOT * HEADS + 255) / 256, 256>>>(ei, as1, ad1, e1, mx1);
    edge_pass_b<HEADS><<<(NE_TOT * HEADS + 255) / 256, 256>>>(ei, e1, mx1, ex1, den1);
    aggregate<HEADS, HID><<<(NE_TOT * HEADS + 7) / 8, 256>>>(ei, h1, ex1, den1, out + A1_OFF, agg1);
    elu_bias<<<(N_NODES * L1_F + 255) / 256, 256>>>(b1);

    /* layer 2 */
    sgemm<<<dim3(OUT_CH / BN, (N_NODES + BM - 1) / BM), 256>>>(agg1, W2, h2, N_NODES, OUT_CH, L1_F);
    attn_coef<1, OUT_CH><<<(N_NODES + 7) / 8, 256>>>(h2, a_src2, a_dst2, as2, ad2);
    edge_pass_a<1><<<(NE_TOT + 255) / 256, 256>>>(ei, as2, ad2, e2, mx2);
    edge_pass_b<1><<<(NE_TOT + 255) / 256, 256>>>(ei, e2, mx2, ex2, den2);
    aggregate<1, OUT_CH><<<(NE_TOT + 7) / 8, 256>>>(ei, h2, ex2, den2, out + A2_OFF, out);
}

// round 2
// speedup vs baseline: 1.7761x; 1.7761x over previous
#include <cuda_runtime.h>
#include <math.h>

#define N_NODES 20000
#define N_EDGES 320000
#define NE_TOT  (N_EDGES + N_NODES)   /* 340000 incl self loops */
#define IN_CH   512
#define HID     128
#define HEADS   4
#define OUT_CH  256
#define L1_F    (HEADS * HID)         /* 512 */

#define A1_OFF  (N_NODES * OUT_CH)            /* 5,120,000 */
#define A2_OFF  (A1_OFF + NE_TOT * HEADS)     /* 6,480,000 */

/* ------------------------- scratch (device globals) ------------------------- */
__device__ float g_h1[(size_t)N_NODES * L1_F];
__device__ float g_agg1[(size_t)N_NODES * L1_F];
__device__ float g_h2[(size_t)N_NODES * OUT_CH];
__device__ float g_as1[N_NODES * HEADS];
__device__ float g_ad1[N_NODES * HEADS];
__device__ float g_as2[N_NODES];
__device__ float g_ad2[N_NODES];
__device__ int   g_counts[N_NODES];
__device__ int   g_cursor[N_NODES];
__device__ int   g_rowptr[N_NODES + 1];
__device__ int   g_esrc[NE_TOT];
__device__ int   g_eorig[NE_TOT];

/* ------------------------- f32x2 helpers ------------------------- */
__device__ __forceinline__ unsigned long long pack2(float lo, float hi) {
    unsigned long long d;
    asm("mov.b64 %0, {%1, %2};" : "=l"(d) : "f"(lo), "f"(hi));
    return d;
}
__device__ __forceinline__ void unpack2(float& lo, float& hi, unsigned long long v) {
    asm("mov.b64 {%0, %1}, %2;" : "=f"(lo), "=f"(hi) : "l"(v));
}
__device__ __forceinline__ unsigned long long fma2(unsigned long long a,
                                                   unsigned long long b,
                                                   unsigned long long c) {
    unsigned long long d;
    asm("fma.rn.f32x2 %0, %1, %2, %3;" : "=l"(d) : "l"(a), "l"(b), "l"(c));
    return d;
}

/* ------------------------- CSR construction ------------------------- */
__device__ __forceinline__ void edge_nodes(const int* __restrict__ ei, int e,
                                           int& src, int& dst) {
    if (e < N_EDGES) { src = ei[e]; dst = ei[N_EDGES + e]; }
    else             { src = dst = e - N_EDGES; }
}

__global__ void zero_counts() {
    int i = blockIdx.x * blockDim.x + threadIdx.x;
    if (i < N_NODES) { g_counts[i] = 0; g_cursor[i] = 0; }
}

__global__ void count_deg(const int* __restrict__ ei) {
    int e = blockIdx.x * blockDim.x + threadIdx.x;
    if (e >= NE_TOT) return;
    int src, dst;
    edge_nodes(ei, e, src, dst);
    atomicAdd(&g_counts[dst], 1);
}

__global__ void scan_rowptr() {
    __shared__ int sh[1024];
    __shared__ int s_carry;
    if (threadIdx.x == 0) { g_rowptr[0] = 0; s_carry = 0; }
    __syncthreads();
    for (int base = 0; base < N_NODES; base += 1024) {
        int i = base + threadIdx.x;
        int v = (i < N_NODES) ? g_counts[i] : 0;
        sh[threadIdx.x] = v;
        __syncthreads();
#pragma unroll
        for (int off = 1; off < 1024; off <<= 1) {
            int t = (threadIdx.x >= off) ? sh[threadIdx.x - off] : 0;
            __syncthreads();
            sh[threadIdx.x] += t;
            __syncthreads();
        }
        int inc = sh[threadIdx.x] + s_carry;
        if (i < N_NODES) g_rowptr[i + 1] = inc;
        __syncthreads();
        if (threadIdx.x == 1023) s_carry = inc;
        __syncthreads();
    }
}

__global__ void scatter_edges(const int* __restrict__ ei) {
    int e = blockIdx.x * blockDim.x + threadIdx.x;
    if (e >= NE_TOT) return;
    int src, dst;
    edge_nodes(ei, e, src, dst);
    int pos = g_rowptr[dst] + atomicAdd(&g_cursor[dst], 1);
    g_esrc[pos]  = src;
    g_eorig[pos] = e;
}

/* ------------------------- SGEMM (fp32, f32x2 FMA, double-buffered) ------- */
#define BM 128
#define BN 128
#define BK 16
#define APAD 132

__global__ __launch_bounds__(256)
void sgemm(const float* __restrict__ A, const float* __restrict__ B,
           float* __restrict__ C, int M, int N, int K) {
    __shared__ float As[2][BK][APAD];
    __shared__ float Bs[2][BK][BN];

    int m0 = blockIdx.y * BM;
    int n0 = blockIdx.x * BN;
    int tid = threadIdx.x;
    int tx = tid & 15, ty = tid >> 4;

    /* per-thread tile-load coordinates */
    int ar0 = tid >> 2,            ac0 = (tid & 3) * 4;
    int ar1 = (tid + 256) >> 2,    ac1 = ((tid + 256) & 3) * 4;
    int br0 = tid >> 5,            bc0 = (tid & 31) * 4;
    int br1 = (tid + 256) >> 5,    bc1 = ((tid + 256) & 31) * 4;

    unsigned long long acc[8][4];
#pragma unroll
    for (int i = 0; i < 8; i++)
#pragma unroll
        for (int j = 0; j < 4; j++) acc[i][j] = 0ull;

    int nt = K / BK;

    /* preload tile 0 into buffer 0 */
    {
        float4 ra0 = make_float4(0.f,0.f,0.f,0.f), ra1 = ra0;
        if (m0 + ar0 < M) ra0 = *(const float4*)(A + (size_t)(m0 + ar0) * K + ac0);
        if (m0 + ar1 < M) ra1 = *(const float4*)(A + (size_t)(m0 + ar1) * K + ac1);
        float4 rb0 = *(const float4*)(B + (size_t)br0 * N + n0 + bc0);
        float4 rb1 = *(const float4*)(B + (size_t)br1 * N + n0 + bc1);
        As[0][ac0+0][ar0]=ra0.x; As[0][ac0+1][ar0]=ra0.y; As[0][ac0+2][ar0]=ra0.z; As[0][ac0+3][ar0]=ra0.w;
        As[0][ac1+0][ar1]=ra1.x; As[0][ac1+1][ar1]=ra1.y; As[0][ac1+2][ar1]=ra1.z; As[0][ac1+3][ar1]=ra1.w;
        *(float4*)&Bs[0][br0][bc0] = rb0;
        *(float4*)&Bs[0][br1][bc1] = rb1;
    }
    __syncthreads();

    for (int t = 0; t < nt; t++) {
        int cur = t & 1;
        bool pf = (t + 1 < nt);
        float4 ra0, ra1, rb0, rb1;
        if (pf) {
            int k0 = (t + 1) * BK;
            ra0 = make_float4(0.f,0.f,0.f,0.f); ra1 = ra0;
            if (m0 + ar0 < M) ra0 = *(const float4*)(A + (size_t)(m0 + ar0) * K + k0 + ac0);
            if (m0 + ar1 < M) ra1 = *(const float4*)(A + (size_t)(m0 + ar1) * K + k0 + ac1);
            rb0 = *(const float4*)(B + (size_t)(k0 + br0) * N + n0 + bc0);
            rb1 = *(const float4*)(B + (size_t)(k0 + br1) * N + n0 + bc1);
        }

#pragma unroll
        for (int k = 0; k < BK; k++) {
            float4 a0 = *(const float4*)&As[cur][k][ty * 8];
            float4 a1 = *(const float4*)&As[cur][k][ty * 8 + 4];
            float4 b0 = *(const float4*)&Bs[cur][k][tx * 8];
            float4 b1 = *(const float4*)&Bs[cur][k][tx * 8 + 4];
            unsigned long long bp[4] = { pack2(b0.x, b0.y), pack2(b0.z, b0.w),
                                         pack2(b1.x, b1.y), pack2(b1.z, b1.w) };
            float av[8] = { a0.x, a0.y, a0.z, a0.w, a1.x, a1.y, a1.z, a1.w };
#pragma unroll
            for (int i = 0; i < 8; i++) {
                unsigned long long ap = pack2(av[i], av[i]);
#pragma unroll
                for (int j = 0; j < 4; j++) acc[i][j] = fma2(ap, bp[j], acc[i][j]);
            }
        }

        if (pf) {
            int nb = cur ^ 1;
            As[nb][ac0+0][ar0]=ra0.x; As[nb][ac0+1][ar0]=ra0.y; As[nb][ac0+2][ar0]=ra0.z; As[nb][ac0+3][ar0]=ra0.w;
            As[nb][ac1+0][ar1]=ra1.x; As[nb][ac1+1][ar1]=ra1.y; As[nb][ac1+2][ar1]=ra1.z; As[nb][ac1+3][ar1]=ra1.w;
            *(float4*)&Bs[nb][br0][bc0] = rb0;
            *(float4*)&Bs[nb][br1][bc1] = rb1;
        }
        __syncthreads();
    }

#pragma unroll
    for (int i = 0; i < 8; i++) {
        int m = m0 + ty * 8 + i;
        if (m < M) {
            float o[8];
#pragma unroll
            for (int j = 0; j < 4; j++) unpack2(o[2 * j], o[2 * j + 1], acc[i][j]);
            float* cp = C + (size_t)m * N + n0 + tx * 8;
            *(float4*)cp       = make_float4(o[0], o[1], o[2], o[3]);
            *(float4*)(cp + 4) = make_float4(o[4], o[5], o[6], o[7]);
        }
    }
}

/* ------------------------- attention coefficients ------------------------- */
template <int H, int C>
__global__ void attn_coef(const float* __restrict__ h,
                          const float* __restrict__ a_src,
                          const float* __restrict__ a_dst,
                          float* __restrict__ as, float* __restrict__ ad) {
    int gw = (blockIdx.x * blockDim.x + threadIdx.x) >> 5;
    int lane = threadIdx.x & 31;
    if (gw >= N_NODES * H) return;
    int n = gw / H, hh = gw % H;
    const float* hp = h + (size_t)n * (H * C) + hh * C;
    const float* sp = a_src + hh * C;
    const float* dp = a_dst + hh * C;
    float s = 0.f, d = 0.f;
#pragma unroll
    for (int c = lane; c < C; c += 32) {
        float v = hp[c];
        s += v * sp[c];
        d += v * dp[c];
    }
#pragma unroll
    for (int o = 16; o; o >>= 1) {
        s += __shfl_xor_sync(0xFFFFFFFFu, s, o);
        d += __shfl_xor_sync(0xFFFFFFFFu, d, o);
    }
    if (lane == 0) { as[gw] = s; ad[gw] = d; }
}

/* ------------------------- fused softmax + aggregate -------------------------
   warp per (dst, head). CSR over incoming edges. Register accumulation, no
   atomics. Epilogue applies bias (+ELU for layer 1). */
template <int H, int C, bool ELU>
__global__ __launch_bounds__(256)
void fused_agg(const float* __restrict__ as, const float* __restrict__ ad,
               const float* __restrict__ hfeat, const float* __restrict__ bias,
               float* __restrict__ alpha_out, float* __restrict__ aggout) {
    int gw = (blockIdx.x * blockDim.x + threadIdx.x) >> 5;
    int lane = threadIdx.x & 31;
    if (gw >= N_NODES * H) return;
    int dst = gw / H, hh = gw % H;

    int beg = g_rowptr[dst], end = g_rowptr[dst + 1];
    float adv = ad[dst * H + hh];

    /* pass 1: max */
    float mx = -1e30f;
    for (int i = beg + lane; i < end; i += 32) {
        float v = as[g_esrc[i] * H + hh] + adv;
        v = v > 0.f ? v : 0.2f * v;
        mx = fmaxf(mx, v);
    }
#pragma unroll
    for (int o = 16; o; o >>= 1) mx = fmaxf(mx, __shfl_xor_sync(0xFFFFFFFFu, mx, o));

    /* pass 2: denom */
    float sm = 0.f;
    for (int i = beg + lane; i < end; i += 32) {
        float v = as[g_esrc[i] * H + hh] + adv;
        v = v > 0.f ? v : 0.2f * v;
        sm += __expf(v - mx);
    }
#pragma unroll
    for (int o = 16; o; o >>= 1) sm += __shfl_xor_sync(0xFFFFFFFFu, sm, o);
    float inv = 1.f / sm;

    /* pass 3: alpha + gather-accumulate (software pipelined, depth 2) */
    constexpr int R = C / 128;
    float4 acc[R];
#pragma unroll
    for (int r = 0; r < R; r++) acc[r] = make_float4(0.f, 0.f, 0.f, 0.f);

    int i = beg;
    int s = g_esrc[i];
    int eo = g_eorig[i];
    float asv = as[s * H + hh];
    float4 tv[R];
    {
        const float4* hp = (const float4*)(hfeat + (size_t)s * (H * C) + hh * C);
#pragma unroll
        for (int r = 0; r < R; r++) tv[r] = hp[lane + 32 * r];
    }
    for (;;) {
        int inext = i + 1;
        bool more = inext < end;
        int s2 = 0, eo2 = 0;
        float asv2 = 0.f;
        float4 tv2[R];
        if (more) {
            s2 = g_esrc[inext];
            eo2 = g_eorig[inext];
            asv2 = as[s2 * H + hh];
            const float4* hp2 = (const float4*)(hfeat + (size_t)s2 * (H * C) + hh * C);
#pragma unroll
            for (int r = 0; r < R; r++) tv2[r] = hp2[lane + 32 * r];
        }
        float v = asv + adv;
        v = v > 0.f ? v : 0.2f * v;
        float a = __expf(v - mx) * inv;
        if (lane == 0) alpha_out[eo * H + hh] = a;
#pragma unroll
        for (int r = 0; r < R; r++) {
            acc[r].x += a * tv[r].x;
            acc[r].y += a * tv[r].y;
            acc[r].z += a * tv[r].z;
            acc[r].w += a * tv[r].w;
        }
        if (!more) break;
        s = s2; eo = eo2; asv = asv2;
#pragma unroll
        for (int r = 0; r < R; r++) tv[r] = tv2[r];
        i = inext;
    }

    /* epilogue: bias (+ELU) */
    float* op = aggout + (size_t)dst * (H * C) + hh * C;
#pragma unroll
    for (int r = 0; r < R; r++) {
        int c = (lane + 32 * r) * 4;
        const float* bp = bias + hh * C + c;
        float4 o = acc[r];
        o.x += bp[0]; o.y += bp[1]; o.z += bp[2]; o.w += bp[3];
        if (ELU) {
            o.x = o.x > 0.f ? o.x : expm1f(o.x);
            o.y = o.y > 0.f ? o.y : expm1f(o.y);
            o.z = o.z > 0.f ? o.z : expm1f(o.z);
            o.w = o.w > 0.f ? o.w : expm1f(o.w);
        }
        ((float4*)op)[lane + 32 * r] = o;
    }
}

/* ------------------------- launch ------------------------- */
extern "C" void kernel_launch(void* const* d_in, const int* in_sizes, int n_in,
                              void* d_out, int out_size) {
    const float* x      = (const float*)d_in[0];
    const int*   ei     = (const int*)  d_in[1];
    const float* W1     = (const float*)d_in[2];
    const float* a_src1 = (const float*)d_in[3];
    const float* a_dst1 = (const float*)d_in[4];
    const float* b1     = (const float*)d_in[5];
    const float* W2     = (const float*)d_in[6];
    const float* a_src2 = (const float*)d_in[7];
    const float* a_dst2 = (const float*)d_in[8];
    const float* b2     = (const float*)d_in[9];
    float* out = (float*)d_out;

    float *h1, *agg1, *h2, *as1, *ad1, *as2, *ad2;
    cudaGetSymbolAddress((void**)&h1,   g_h1);
    cudaGetSymbolAddress((void**)&agg1, g_agg1);
    cudaGetSymbolAddress((void**)&h2,   g_h2);
    cudaGetSymbolAddress((void**)&as1,  g_as1);
    cudaGetSymbolAddress((void**)&ad1,  g_ad1);
    cudaGetSymbolAddress((void**)&as2,  g_as2);
    cudaGetSymbolAddress((void**)&ad2,  g_ad2);

    /* CSR build (shared by both layers) */
    zero_counts<<<(N_NODES + 255) / 256, 256>>>();
    count_deg<<<(NE_TOT + 255) / 256, 256>>>(ei);
    scan_rowptr<<<1, 1024>>>();
    scatter_edges<<<(NE_TOT + 255) / 256, 256>>>(ei);

    /* layer 1 */
    sgemm<<<dim3(L1_F / BN, (N_NODES + BM - 1) / BM), 256>>>(x, W1, h1, N_NODES, L1_F, IN_CH);
    attn_coef<HEADS, HID><<<(N_NODES * HEADS + 7) / 8, 256>>>(h1, a_src1, a_dst1, as1, ad1);
    fused_agg<HEADS, HID, true><<<(N_NODES * HEADS + 7) / 8, 256>>>(
        as1, ad1, h1, b1, out + A1_OFF, agg1);

    /* layer 2 */
    sgemm<<<dim3(OUT_CH / BN, (N_NODES + BM - 1) / BM), 256>>>(agg1, W2, h2, N_NODES, OUT_CH, L1_F);
    attn_coef<1, OUT_CH><<<(N_NODES + 7) / 8, 256>>>(h2, a_src2, a_dst2, as2, ad2);
    fused_agg<1, OUT_CH, false><<<(N_NODES + 7) / 8, 256>>>(
        as2, ad2, h2, b2, out + A2_OFF, out);
}

// round 4
// speedup vs baseline: 2.5810x; 1.4531x over previous
#include <cuda_runtime.h>
#include <cuda_bf16.h>
#include <math.h>
#include <stdint.h>

#define N_NODES 20000
#define N_EDGES 320000
#define NE_TOT  (N_EDGES + N_NODES)   /* 340000 incl self loops */
#define IN_CH   512
#define HID     128
#define HEADS   4
#define OUT_CH  256
#define L1_F    (HEADS * HID)         /* 512 */

#define A1_OFF  (N_NODES * OUT_CH)            /* 5,120,000 */
#define A2_OFF  (A1_OFF + NE_TOT * HEADS)     /* 6,480,000 */

/* ------------------------- scratch (device globals) ------------------------- */
__device__ float         g_h1[(size_t)N_NODES * L1_F];
__device__ float         g_h2[(size_t)N_NODES * OUT_CH];
__device__ __nv_bfloat16 g_xhi[(size_t)N_NODES * IN_CH];
__device__ __nv_bfloat16 g_xlo[(size_t)N_NODES * IN_CH];
__device__ __nv_bfloat16 g_w1hi[L1_F * IN_CH];      /* transposed [N][K] */
__device__ __nv_bfloat16 g_w1lo[L1_F * IN_CH];
__device__ __nv_bfloat16 g_w2hi[OUT_CH * L1_F];
__device__ __nv_bfloat16 g_w2lo[OUT_CH * L1_F];
__device__ __nv_bfloat16 g_a1hi[(size_t)N_NODES * L1_F];
__device__ __nv_bfloat16 g_a1lo[(size_t)N_NODES * L1_F];
__device__ float g_as1[N_NODES * HEADS];
__device__ float g_ad1[N_NODES * HEADS];
__device__ float g_as2[N_NODES];
__device__ float g_ad2[N_NODES];
__device__ int   g_counts[N_NODES];
__device__ int   g_cursor[N_NODES];
__device__ int   g_rowptr[N_NODES + 1];
__device__ int   g_esrc[NE_TOT];
__device__ int   g_eorig[NE_TOT];

/* ------------------------- helpers ------------------------- */
__device__ __forceinline__ uint32_t smem_u32(const void* p) {
    uint32_t a;
    asm("{ .reg .u64 t; cvta.to.shared.u64 t, %1; cvt.u32.u64 %0, t; }" : "=r"(a) : "l"(p));
    return a;
}
__device__ __forceinline__ void ldsm_x4(uint32_t& r0, uint32_t& r1, uint32_t& r2,
                                        uint32_t& r3, uint32_t addr) {
    asm volatile("ldmatrix.sync.aligned.m8n8.x4.shared.b16 {%0,%1,%2,%3}, [%4];"
                 : "=r"(r0), "=r"(r1), "=r"(r2), "=r"(r3) : "r"(addr));
}
__device__ __forceinline__ void mma_bf16(float* d, const uint32_t* a, const uint32_t* b) {
    asm volatile("mma.sync.aligned.m16n8k16.row.col.f32.bf16.bf16.f32 "
                 "{%0,%1,%2,%3}, {%4,%5,%6,%7}, {%8,%9}, {%0,%1,%2,%3};"
                 : "+f"(d[0]), "+f"(d[1]), "+f"(d[2]), "+f"(d[3])
                 : "r"(a[0]), "r"(a[1]), "r"(a[2]), "r"(a[3]), "r"(b[0]), "r"(b[1]));
}

/* ------------------------- CSR construction ------------------------- */
__device__ __forceinline__ void edge_nodes(const int* __restrict__ ei, int e,
                                           int& src, int& dst) {
    if (e < N_EDGES) { src = ei[e]; dst = ei[N_EDGES + e]; }
    else             { src = dst = e - N_EDGES; }
}

__global__ void zero_counts() {
    int i = blockIdx.x * blockDim.x + threadIdx.x;
    if (i < N_NODES) { g_counts[i] = 0; g_cursor[i] = 0; }
}

__global__ void count_deg(const int* __restrict__ ei) {
    int e = blockIdx.x * blockDim.x + threadIdx.x;
    if (e >= NE_TOT) return;
    int src, dst;
    edge_nodes(ei, e, src, dst);
    atomicAdd(&g_counts[dst], 1);
}

__global__ void scan_rowptr() {
    __shared__ int wsum[32];
    __shared__ int s_carry;
    int tid = threadIdx.x, lane = tid & 31, wid = tid >> 5;
    if (tid == 0) { g_rowptr[0] = 0; s_carry = 0; }
    __syncthreads();
    for (int base = 0; base < N_NODES; base += 1024) {
        int i = base + tid;
        int v = (i < N_NODES) ? g_counts[i] : 0;
        int x = v;
#pragma unroll
        for (int o = 1; o < 32; o <<= 1) {
            int t = __shfl_up_sync(0xFFFFFFFFu, x, o);
            if (lane >= o) x += t;
        }
        if (lane == 31) wsum[wid] = x;
        __syncthreads();
        if (wid == 0) {
            int s = wsum[lane];
#pragma unroll
            for (int o = 1; o < 32; o <<= 1) {
                int t = __shfl_up_sync(0xFFFFFFFFu, s, o);
                if (lane >= o) s += t;
            }
            wsum[lane] = s;
        }
        __syncthreads();
        int inc = x + (wid > 0 ? wsum[wid - 1] : 0) + s_carry;
        if (i < N_NODES) g_rowptr[i + 1] = inc;
        __syncthreads();
        if (tid == 1023) s_carry = inc;
        __syncthreads();
    }
}

__global__ void scatter_edges(const int* __restrict__ ei) {
    int e = blockIdx.x * blockDim.x + threadIdx.x;
    if (e >= NE_TOT) return;
    int src, dst;
    edge_nodes(ei, e, src, dst);
    int pos = g_rowptr[dst] + atomicAdd(&g_cursor[dst], 1);
    g_esrc[pos]  = src;
    g_eorig[pos] = e;
}

/* ------------------------- fp32 -> bf16 hi/lo splits ------------------------- */
__global__ void split_fp32(const float* __restrict__ in,
                           __nv_bfloat16* __restrict__ hi,
                           __nv_bfloat16* __restrict__ lo, int n) {
    int i = blockIdx.x * blockDim.x + threadIdx.x;
    if (i >= n) return;
    float v = in[i];
    __nv_bfloat16 h = __float2bfloat16(v);
    hi[i] = h;
    lo[i] = __float2bfloat16(v - __bfloat162float(h));
}

/* W [K][N] -> out [N][K] bf16 hi/lo */
__global__ void split_w_t(const float* __restrict__ W,
                          __nv_bfloat16* __restrict__ thi,
                          __nv_bfloat16* __restrict__ tlo, int K, int N) {
    int i = blockIdx.x * blockDim.x + threadIdx.x;
    if (i >= K * N) return;
    int k = i / N, n = i % N;
    float v = W[i];
    __nv_bfloat16 h = __float2bfloat16(v);
    thi[n * K + k] = h;
    tlo[n * K + k] = __float2bfloat16(v - __bfloat162float(h));
}

/* ------------------------- HMMA bf16-split GEMM -------------------------
   C[M,N] fp32 ≈ Ahi*Bhi^T + Alo*Bhi^T + Ahi*Blo^T; A [M,K], B [N,K] bf16.
   K=512. CTA tile 128x128, 8 warps (4m x 2n), warp tile 32x64.
   Smem rows padded to 24 halves (48B stride, conflict-free ldmatrix). */
#define KSTAGES (512 / 16)    /* 32 */
#define SROW    24

__global__ __launch_bounds__(256)
void gemm_hmma(const __nv_bfloat16* __restrict__ Ahi, const __nv_bfloat16* __restrict__ Alo,
               const __nv_bfloat16* __restrict__ Bhi, const __nv_bfloat16* __restrict__ Blo,
               float* __restrict__ C, int M, int N) {
    __shared__ __align__(16) __nv_bfloat16 sA[2][2][128][SROW]; /* [buf][hi/lo] */
    __shared__ __align__(16) __nv_bfloat16 sB[2][2][128][SROW];

    int tid = threadIdx.x, wid = tid >> 5, lane = tid & 31;
    int m0 = blockIdx.y * 128, n0 = blockIdx.x * 128;
    int wm = (wid >> 1) * 32;           /* warp m offset in tile */
    int wn = (wid & 1) * 64;            /* warp n offset in tile */

    /* gmem prefetch coords: thread loads one uint4 (8 halves) per matrix */
    int prow = tid >> 1, pseg = tid & 1;           /* row 0..127, k-seg 0..1 */
    int agr = m0 + prow; if (agr >= M) agr = M - 1;
    const uint4* gAhi = (const uint4*)(Ahi + (size_t)agr * 512 + pseg * 8);
    const uint4* gAlo = (const uint4*)(Alo + (size_t)agr * 512 + pseg * 8);
    const uint4* gBhi = (const uint4*)(Bhi + (size_t)(n0 + prow) * 512 + pseg * 8);
    const uint4* gBlo = (const uint4*)(Blo + (size_t)(n0 + prow) * 512 + pseg * 8);
    uint32_t sAoff = smem_u32(&sA[0][0][prow][pseg * 8]);
    uint32_t sBoff = smem_u32(&sB[0][0][prow][pseg * 8]);

    /* ldmatrix lane addresses (byte offsets inside one [hi/lo] plane) */
    int a_row = (lane & 15), a_k = (lane >> 4) * 8;
    int b_nrow = ((lane >> 4) << 3) + (lane & 7), b_k = ((lane >> 3) & 1) * 8;
    uint32_t a_base0 = smem_u32(&sA[0][0][wm + a_row][a_k]);
    uint32_t a_base1 = smem_u32(&sA[0][1][wm + a_row][a_k]);
    uint32_t b_base0 = smem_u32(&sB[0][0][wn + b_nrow][b_k]);
    uint32_t b_base1 = smem_u32(&sB[0][1][wn + b_nrow][b_k]);
    const uint32_t BUFSTRIDE = 2 * 128 * SROW * 2;   /* bytes between buffers */

    float acc[2][8][4];
#pragma unroll
    for (int i = 0; i < 2; i++)
#pragma unroll
        for (int j = 0; j < 8; j++)
#pragma unroll
            for (int q = 0; q < 4; q++) acc[i][j][q] = 0.f;

    /* preload stage 0 */
    {
        uint4 va = gAhi[0], vb = gAlo[0], vc = gBhi[0], vd = gBlo[0];
        *(uint4*)(sA[0][0][prow] + pseg * 8) = va;
        *(uint4*)(sA[0][1][prow] + pseg * 8) = vb;
        *(uint4*)(sB[0][0][prow] + pseg * 8) = vc;
        *(uint4*)(sB[0][1][prow] + pseg * 8) = vd;
    }
    __syncthreads();

    for (int t = 0; t < KSTAGES; t++) {
        int buf = t & 1;
        uint4 va, vb, vc, vd;
        bool pf = (t + 1 < KSTAGES);
        if (pf) {
            int koff4 = (t + 1) * 2;         /* uint4 index along k */
            va = gAhi[koff4]; vb = gAlo[koff4];
            vc = gBhi[koff4]; vd = gBlo[koff4];
        }

        uint32_t abase = buf * BUFSTRIDE;
        /* A frags: 2 m-atoms, hi+lo */
        uint32_t ahi[2][4], alo[2][4];
#pragma unroll
        for (int ma = 0; ma < 2; ma++) {
            ldsm_x4(ahi[ma][0], ahi[ma][1], ahi[ma][2], ahi[ma][3],
                    a_base0 + abase + ma * 16 * SROW * 2);
            ldsm_x4(alo[ma][0], alo[ma][1], alo[ma][2], alo[ma][3],
                    a_base1 + abase + ma * 16 * SROW * 2);
        }
        /* B frags: 4 n16-groups (8 n-atoms), hi+lo */
        uint32_t bhi[4][4], blo[4][4];
#pragma unroll
        for (int g = 0; g < 4; g++) {
            ldsm_x4(bhi[g][0], bhi[g][1], bhi[g][2], bhi[g][3],
                    b_base0 + abase + g * 16 * SROW * 2);
            ldsm_x4(blo[g][0], blo[g][1], blo[g][2], blo[g][3],
                    b_base1 + abase + g * 16 * SROW * 2);
        }

#pragma unroll
        for (int ma = 0; ma < 2; ma++)
#pragma unroll
            for (int g = 0; g < 4; g++)
#pragma unroll
                for (int h = 0; h < 2; h++) {
                    float* d = acc[ma][g * 2 + h];
                    mma_bf16(d, ahi[ma], &bhi[g][h * 2]);
                    mma_bf16(d, alo[ma], &bhi[g][h * 2]);
                    mma_bf16(d, ahi[ma], &blo[g][h * 2]);
                }

        if (pf) {
            uint32_t nb = (buf ^ 1) * BUFSTRIDE;
            *(uint4*)(uintptr_t(sA) + 0)                 ; /* no-op to keep types honest */
            /* store via computed smem addresses */
            *(uint4*)((char*)sA + (sAoff - smem_u32(sA)) + nb) = va;
            *(uint4*)((char*)sA + (sAoff - smem_u32(sA)) + nb + 128 * SROW * 2) = vb;
            *(uint4*)((char*)sB + (sBoff - smem_u32(sB)) + nb) = vc;
            *(uint4*)((char*)sB + (sBoff - smem_u32(sB)) + nb + 128 * SROW * 2) = vd;
        }
        __syncthreads();
    }

    /* epilogue: write fp32 C */
    int lg = lane >> 2, lt = lane & 3;
#pragma unroll
    for (int ma = 0; ma < 2; ma++) {
        int mrow0 = m0 + wm + ma * 16 + lg;
#pragma unroll
        for (int nb = 0; nb < 8; nb++) {
            int n = n0 + wn + nb * 8 + lt * 2;
            float* d = acc[ma][nb];
            if (mrow0 < M)
                *(float2*)(C + (size_t)mrow0 * N + n) = make_float2(d[0], d[1]);
            if (mrow0 + 8 < M)
                *(float2*)(C + (size_t)(mrow0 + 8) * N + n) = make_float2(d[2], d[3]);
        }
    }
}

/* ------------------------- attention coefficients ------------------------- */
template <int H, int C>
__global__ void attn_coef(const float* __restrict__ h,
                          const float* __restrict__ a_src,
                          const float* __restrict__ a_dst,
                          float* __restrict__ as, float* __restrict__ ad) {
    int gw = (blockIdx.x * blockDim.x + threadIdx.x) >> 5;
    int lane = threadIdx.x & 31;
    if (gw >= N_NODES * H) return;
    int n = gw / H, hh = gw % H;
    const float* hp = h + (size_t)n * (H * C) + hh * C;
    const float* sp = a_src + hh * C;
    const float* dp = a_dst + hh * C;
    float s = 0.f, d = 0.f;
#pragma unroll
    for (int c = lane; c < C; c += 32) {
        float v = hp[c];
        s += v * sp[c];
        d += v * dp[c];
    }
#pragma unroll
    for (int o = 16; o; o >>= 1) {
        s += __shfl_xor_sync(0xFFFFFFFFu, s, o);
        d += __shfl_xor_sync(0xFFFFFFFFu, d, o);
    }
    if (lane == 0) { as[gw] = s; ad[gw] = d; }
}

/* ------------------------- fused softmax + aggregate ------------------------- */
template <int H, int C, bool ELU, bool SPLIT>
__global__ __launch_bounds__(256)
void fused_agg(const float* __restrict__ as, const float* __restrict__ ad,
               const float* __restrict__ hfeat, const float* __restrict__ bias,
               float* __restrict__ alpha_out, float* __restrict__ aggout,
               __nv_bfloat16* __restrict__ ohi, __nv_bfloat16* __restrict__ olo) {
    int gw = (blockIdx.x * blockDim.x + threadIdx.x) >> 5;
    int lane = threadIdx.x & 31;
    if (gw >= N_NODES * H) return;
    int dst = gw / H, hh = gw % H;

    int beg = g_rowptr[dst], end = g_rowptr[dst + 1];
    float adv = ad[dst * H + hh];

    float mx = -1e30f;
    for (int i = beg + lane; i < end; i += 32) {
        float v = as[g_esrc[i] * H + hh] + adv;
        v = v > 0.f ? v : 0.2f * v;
        mx = fmaxf(mx, v);
    }
#pragma unroll
    for (int o = 16; o; o >>= 1) mx = fmaxf(mx, __shfl_xor_sync(0xFFFFFFFFu, mx, o));

    float sm = 0.f;
    for (int i = beg + lane; i < end; i += 32) {
        float v = as[g_esrc[i] * H + hh] + adv;
        v = v > 0.f ? v : 0.2f * v;
        sm += __expf(v - mx);
    }
#pragma unroll
    for (int o = 16; o; o >>= 1) sm += __shfl_xor_sync(0xFFFFFFFFu, sm, o);
    float inv = 1.f / sm;

    constexpr int R = C / 128;
    float4 acc[R];
#pragma unroll
    for (int r = 0; r < R; r++) acc[r] = make_float4(0.f, 0.f, 0.f, 0.f);

    int i = beg;
    int s = g_esrc[i];
    int eo = g_eorig[i];
    float asv = as[s * H + hh];
    float4 tv[R];
    {
        const float4* hp = (const float4*)(hfeat + (size_t)s * (H * C) + hh * C);
#pragma unroll
        for (int r = 0; r < R; r++) tv[r] = hp[lane + 32 * r];
    }
    for (;;) {
        int inext = i + 1;
        bool more = inext < end;
        int s2 = 0, eo2 = 0;
        float asv2 = 0.f;
        float4 tv2[R];
        if (more) {
            s2 = g_esrc[inext];
            eo2 = g_eorig[inext];
            asv2 = as[s2 * H + hh];
            const float4* hp2 = (const float4*)(hfeat + (size_t)s2 * (H * C) + hh * C);
#pragma unroll
            for (int r = 0; r < R; r++) tv2[r] = hp2[lane + 32 * r];
        }
        float v = asv + adv;
        v = v > 0.f ? v : 0.2f * v;
        float a = __expf(v - mx) * inv;
        if (lane == 0) alpha_out[eo * H + hh] = a;
#pragma unroll
        for (int r = 0; r < R; r++) {
            acc[r].x += a * tv[r].x;
            acc[r].y += a * tv[r].y;
            acc[r].z += a * tv[r].z;
            acc[r].w += a * tv[r].w;
        }
        if (!more) break;
        s = s2; eo = eo2; asv = asv2;
#pragma unroll
        for (int r = 0; r < R; r++) tv[r] = tv2[r];
        i = inext;
    }

#pragma unroll
    for (int r = 0; r < R; r++) {
        int c = (lane + 32 * r) * 4;
        const float* bp = bias + hh * C + c;
        float4 o = acc[r];
        o.x += bp[0]; o.y += bp[1]; o.z += bp[2]; o.w += bp[3];
        if (ELU) {
            o.x = o.x > 0.f ? o.x : expm1f(o.x);
            o.y = o.y > 0.f ? o.y : expm1f(o.y);
            o.z = o.z > 0.f ? o.z : expm1f(o.z);
            o.w = o.w > 0.f ? o.w : expm1f(o.w);
        }
        if (SPLIT) {
            size_t base = (size_t)dst * (H * C) + hh * C + c;
            float vv[4] = { o.x, o.y, o.z, o.w };
#pragma unroll
            for (int q = 0; q < 4; q++) {
                __nv_bfloat16 h = __float2bfloat16(vv[q]);
                ohi[base + q] = h;
                olo[base + q] = __float2bfloat16(vv[q] - __bfloat162float(h));
            }
        } else {
            float* op = aggout + (size_t)dst * (H * C) + hh * C;
            ((float4*)op)[lane + 32 * r] = o;
        }
    }
}

/* ------------------------- launch ------------------------- */
extern "C" void kernel_launch(void* const* d_in, const int* in_sizes, int n_in,
                              void* d_out, int out_size) {
    const float* x      = (const float*)d_in[0];
    const int*   ei     = (const int*)  d_in[1];
    const float* W1     = (const float*)d_in[2];
    const float* a_src1 = (const float*)d_in[3];
    const float* a_dst1 = (const float*)d_in[4];
    const float* b1     = (const float*)d_in[5];
    const float* W2     = (const float*)d_in[6];
    const float* a_src2 = (const float*)d_in[7];
    const float* a_dst2 = (const float*)d_in[8];
    const float* b2     = (const float*)d_in[9];
    float* out = (float*)d_out;

    float *h1, *h2, *as1, *ad1, *as2, *ad2;
    __nv_bfloat16 *xhi, *xlo, *w1hi, *w1lo, *w2hi, *w2lo, *a1hi, *a1lo;
    cudaGetSymbolAddress((void**)&h1,   g_h1);
    cudaGetSymbolAddress((void**)&h2,   g_h2);
    cudaGetSymbolAddress((void**)&as1,  g_as1);
    cudaGetSymbolAddress((void**)&ad1,  g_ad1);
    cudaGetSymbolAddress((void**)&as2,  g_as2);
    cudaGetSymbolAddress((void**)&ad2,  g_ad2);
    cudaGetSymbolAddress((void**)&xhi,  g_xhi);
    cudaGetSymbolAddress((void**)&xlo,  g_xlo);
    cudaGetSymbolAddress((void**)&w1hi, g_w1hi);
    cudaGetSymbolAddress((void**)&w1lo, g_w1lo);
    cudaGetSymbolAddress((void**)&w2hi, g_w2hi);
    cudaGetSymbolAddress((void**)&w2lo, g_w2lo);
    cudaGetSymbolAddress((void**)&a1hi, g_a1hi);
    cudaGetSymbolAddress((void**)&a1lo, g_a1lo);

    /* CSR build (shared by both layers) */
    zero_counts<<<(N_NODES + 255) / 256, 256>>>();
    count_deg<<<(NE_TOT + 255) / 256, 256>>>(ei);
    scan_rowptr<<<1, 1024>>>();
    scatter_edges<<<(NE_TOT + 255) / 256, 256>>>(ei);

    /* conversions */
    split_fp32<<<(N_NODES * IN_CH + 255) / 256, 256>>>(x, xhi, xlo, N_NODES * IN_CH);
    split_w_t<<<(IN_CH * L1_F + 255) / 256, 256>>>(W1, w1hi, w1lo, IN_CH, L1_F);
    split_w_t<<<(L1_F * OUT_CH + 255) / 256, 256>>>(W2, w2hi, w2lo, L1_F, OUT_CH);

    /* layer 1 */
    gemm_hmma<<<dim3(L1_F / 128, 157), 256>>>(xhi, xlo, w1hi, w1lo, h1, N_NODES, L1_F);
    attn_coef<HEADS, HID><<<(N_NODES * HEADS + 7) / 8, 256>>>(h1, a_src1, a_dst1, as1, ad1);
    fused_agg<HEADS, HID, true, true><<<(N_NODES * HEADS + 7) / 8, 256>>>(
        as1, ad1, h1, b1, out + A1_OFF, nullptr, a1hi, a1lo);

    /* layer 2 */
    gemm_hmma<<<dim3(OUT_CH / 128, 157), 256>>>(a1hi, a1lo, w2hi, w2lo, h2, N_NODES, OUT_CH);
    attn_coef<1, OUT_CH><<<(N_NODES + 7) / 8, 256>>>(h2, a_src2, a_dst2, as2, ad2);
    fused_agg<1, OUT_CH, false, false><<<(N_NODES + 7) / 8, 256>>>(
        as2, ad2, h2, b2, out + A2_OFF, out, nullptr, nullptr);
}

// round 5
// speedup vs baseline: 3.0122x; 1.1671x over previous
#include <cuda_runtime.h>
#include <cuda_bf16.h>
#include <math.h>
#include <stdint.h>

#define N_NODES 20000
#define N_EDGES 320000
#define NE_TOT  (N_EDGES + N_NODES)   /* 340000 incl self loops */
#define IN_CH   512
#define HID     128
#define HEADS   4
#define OUT_CH  256
#define L1_F    (HEADS * HID)         /* 512 */

#define A1_OFF  (N_NODES * OUT_CH)            /* 5,120,000 */
#define A2_OFF  (A1_OFF + NE_TOT * HEADS)     /* 6,480,000 */

/* ------------------------- scratch (device globals) ------------------------- */
__device__ float         g_h1[(size_t)N_NODES * L1_F];
__device__ float         g_h2[(size_t)N_NODES * OUT_CH];
__device__ __nv_bfloat16 g_xhi[(size_t)N_NODES * IN_CH];
__device__ __nv_bfloat16 g_xlo[(size_t)N_NODES * IN_CH];
__device__ __nv_bfloat16 g_w1hi[L1_F * IN_CH];      /* transposed [N][K] */
__device__ __nv_bfloat16 g_w1lo[L1_F * IN_CH];
__device__ __nv_bfloat16 g_w2hi[OUT_CH * L1_F];
__device__ __nv_bfloat16 g_w2lo[OUT_CH * L1_F];
__device__ __nv_bfloat16 g_a1hi[(size_t)N_NODES * L1_F];
__device__ __nv_bfloat16 g_a1lo[(size_t)N_NODES * L1_F];
__device__ float g_as1[N_NODES * HEADS];
__device__ float g_ad1[N_NODES * HEADS];
__device__ float g_as2[N_NODES];
__device__ float g_ad2[N_NODES];
__device__ float g_vbuf[(size_t)NE_TOT * HEADS];    /* [head][csr_pos] */
__device__ int   g_counts[N_NODES];
__device__ int   g_cursor[N_NODES];
__device__ int   g_rowptr[N_NODES + 1];
__device__ int   g_esrc[NE_TOT];
__device__ int   g_eorig[NE_TOT];

/* ------------------------- helpers ------------------------- */
__device__ __forceinline__ uint32_t smem_u32(const void* p) {
    uint32_t a;
    asm("{ .reg .u64 t; cvta.to.shared.u64 t, %1; cvt.u32.u64 %0, t; }" : "=r"(a) : "l"(p));
    return a;
}
__device__ __forceinline__ void ldsm_x4(uint32_t& r0, uint32_t& r1, uint32_t& r2,
                                        uint32_t& r3, uint32_t addr) {
    asm volatile("ldmatrix.sync.aligned.m8n8.x4.shared.b16 {%0,%1,%2,%3}, [%4];"
                 : "=r"(r0), "=r"(r1), "=r"(r2), "=r"(r3) : "r"(addr));
}
__device__ __forceinline__ void mma_bf16(float* d, const uint32_t* a, const uint32_t* b) {
    asm volatile("mma.sync.aligned.m16n8k16.row.col.f32.bf16.bf16.f32 "
                 "{%0,%1,%2,%3}, {%4,%5,%6,%7}, {%8,%9}, {%0,%1,%2,%3};"
                 : "+f"(d[0]), "+f"(d[1]), "+f"(d[2]), "+f"(d[3])
                 : "r"(a[0]), "r"(a[1]), "r"(a[2]), "r"(a[3]), "r"(b[0]), "r"(b[1]));
}
__device__ __forceinline__ void cpa16(uint32_t dst, const void* src) {
    asm volatile("cp.async.cg.shared.global [%0], [%1], 16;" :: "r"(dst), "l"(src));
}
#define CP_COMMIT() asm volatile("cp.async.commit_group;" ::: "memory")
#define CP_WAIT0()  asm volatile("cp.async.wait_group 0;" ::: "memory")

/* ------------------------- CSR construction ------------------------- */
__device__ __forceinline__ void edge_nodes(const int* __restrict__ ei, int e,
                                           int& src, int& dst) {
    if (e < N_EDGES) { src = ei[e]; dst = ei[N_EDGES + e]; }
    else             { src = dst = e - N_EDGES; }
}

__global__ void count_deg(const int* __restrict__ ei) {
    int e = blockIdx.x * blockDim.x + threadIdx.x;
    if (e >= NE_TOT) return;
    int src, dst;
    edge_nodes(ei, e, src, dst);
    atomicAdd(&g_counts[dst], 1);
}

__global__ void scan_rowptr() {
    __shared__ int wsum[32];
    __shared__ int s_carry;
    int tid = threadIdx.x, lane = tid & 31, wid = tid >> 5;
    if (tid == 0) { g_rowptr[0] = 0; s_carry = 0; }
    __syncthreads();
    for (int base = 0; base < N_NODES; base += 1024) {
        int i = base + tid;
        int v = (i < N_NODES) ? g_counts[i] : 0;
        int x = v;
#pragma unroll
        for (int o = 1; o < 32; o <<= 1) {
            int t = __shfl_up_sync(0xFFFFFFFFu, x, o);
            if (lane >= o) x += t;
        }
        if (lane == 31) wsum[wid] = x;
        __syncthreads();
        if (wid == 0) {
            int s = wsum[lane];
#pragma unroll
            for (int o = 1; o < 32; o <<= 1) {
                int t = __shfl_up_sync(0xFFFFFFFFu, s, o);
                if (lane >= o) s += t;
            }
            wsum[lane] = s;
        }
        __syncthreads();
        int inc = x + (wid > 0 ? wsum[wid - 1] : 0) + s_carry;
        if (i < N_NODES) g_rowptr[i + 1] = inc;
        __syncthreads();
        if (tid == 1023) s_carry = inc;
        __syncthreads();
    }
}

__global__ void scatter_edges(const int* __restrict__ ei) {
    int e = blockIdx.x * blockDim.x + threadIdx.x;
    if (e >= NE_TOT) return;
    int src, dst;
    edge_nodes(ei, e, src, dst);
    int pos = g_rowptr[dst] + atomicAdd(&g_cursor[dst], 1);
    g_esrc[pos]  = src;
    g_eorig[pos] = e;
}

/* ------------------------- fp32 -> bf16 hi/lo splits ------------------------- */
/* also zeroes CSR counters (merged launch) */
__global__ void split_fp32_zero(const float* __restrict__ in,
                                __nv_bfloat16* __restrict__ hi,
                                __nv_bfloat16* __restrict__ lo, int n) {
    int i = blockIdx.x * blockDim.x + threadIdx.x;
    if (i < N_NODES) { g_counts[i] = 0; g_cursor[i] = 0; }
    if (i >= n) return;
    float v = in[i];
    __nv_bfloat16 h = __float2bfloat16(v);
    hi[i] = h;
    lo[i] = __float2bfloat16(v - __bfloat162float(h));
}

/* W [K][N] -> out [N][K] bf16 hi/lo */
__global__ void split_w_t(const float* __restrict__ W,
                          __nv_bfloat16* __restrict__ thi,
                          __nv_bfloat16* __restrict__ tlo, int K, int N) {
    int i = blockIdx.x * blockDim.x + threadIdx.x;
    if (i >= K * N) return;
    int k = i / N, n = i % N;
    float v = W[i];
    __nv_bfloat16 h = __float2bfloat16(v);
    thi[n * K + k] = h;
    tlo[n * K + k] = __float2bfloat16(v - __bfloat162float(h));
}

/* ------------------------- HMMA bf16-split GEMM (cp.async) ------------------
   C[M,N] fp32 ≈ Ahi*Bhi^T + Alo*Bhi^T + Ahi*Blo^T; A [M,K], B [N,K] bf16.
   K=512. CTA tile 128x128, 8 warps (4m x 2n), warp tile 32x64.
   Smem rows padded to 24 halves (48B stride, conflict-free ldmatrix). */
#define KSTAGES (512 / 16)    /* 32 */
#define SROW    24

__global__ __launch_bounds__(256)
void gemm_hmma(const __nv_bfloat16* __restrict__ Ahi, const __nv_bfloat16* __restrict__ Alo,
               const __nv_bfloat16* __restrict__ Bhi, const __nv_bfloat16* __restrict__ Blo,
               float* __restrict__ C, int M, int N) {
    __shared__ __align__(16) __nv_bfloat16 sA[2][2][128][SROW]; /* [buf][hi/lo] */
    __shared__ __align__(16) __nv_bfloat16 sB[2][2][128][SROW];

    int tid = threadIdx.x, wid = tid >> 5, lane = tid & 31;
    int m0 = blockIdx.y * 128, n0 = blockIdx.x * 128;
    int wm = (wid >> 1) * 32;
    int wn = (wid & 1) * 64;

    /* gmem load coords: thread loads one 16B chunk per plane per stage */
    int prow = tid >> 1, pseg = tid & 1;
    int agr = m0 + prow; if (agr >= M) agr = M - 1;
    const __nv_bfloat16* pAhi = Ahi + (size_t)agr * 512 + pseg * 8;
    const __nv_bfloat16* pAlo = Alo + (size_t)agr * 512 + pseg * 8;
    const __nv_bfloat16* pBhi = Bhi + (size_t)(n0 + prow) * 512 + pseg * 8;
    const __nv_bfloat16* pBlo = Blo + (size_t)(n0 + prow) * 512 + pseg * 8;
    uint32_t dA0[2], dA1[2], dB0[2], dB1[2];
#pragma unroll
    for (int b = 0; b < 2; b++) {
        dA0[b] = smem_u32(&sA[b][0][prow][pseg * 8]);
        dA1[b] = smem_u32(&sA[b][1][prow][pseg * 8]);
        dB0[b] = smem_u32(&sB[b][0][prow][pseg * 8]);
        dB1[b] = smem_u32(&sB[b][1][prow][pseg * 8]);
    }

    /* ldmatrix lane addresses */
    int a_row = (lane & 15), a_k = (lane >> 4) * 8;
    int b_nrow = ((lane >> 4) << 3) + (lane & 7), b_k = ((lane >> 3) & 1) * 8;
    uint32_t a_base0 = smem_u32(&sA[0][0][wm + a_row][a_k]);
    uint32_t a_base1 = smem_u32(&sA[0][1][wm + a_row][a_k]);
    uint32_t b_base0 = smem_u32(&sB[0][0][wn + b_nrow][b_k]);
    uint32_t b_base1 = smem_u32(&sB[0][1][wn + b_nrow][b_k]);
    const uint32_t BUFSTRIDE = 2 * 128 * SROW * 2;

    float acc[2][8][4];
#pragma unroll
    for (int i = 0; i < 2; i++)
#pragma unroll
        for (int j = 0; j < 8; j++)
#pragma unroll
            for (int q = 0; q < 4; q++) acc[i][j][q] = 0.f;

    /* preload stage 0 */
    cpa16(dA0[0], pAhi);
    cpa16(dA1[0], pAlo);
    cpa16(dB0[0], pBhi);
    cpa16(dB1[0], pBlo);
    CP_COMMIT();
    CP_WAIT0();
    __syncthreads();

    for (int t = 0; t < KSTAGES; t++) {
        int buf = t & 1;
        if (t + 1 < KSTAGES) {
            int nb = (t + 1) & 1, ko = (t + 1) * 16;
            cpa16(dA0[nb], pAhi + ko);
            cpa16(dA1[nb], pAlo + ko);
            cpa16(dB0[nb], pBhi + ko);
            cpa16(dB1[nb], pBlo + ko);
            CP_COMMIT();
        }

        uint32_t abase = buf * BUFSTRIDE;
        uint32_t ahi[2][4], alo[2][4];
#pragma unroll
        for (int ma = 0; ma < 2; ma++) {
            ldsm_x4(ahi[ma][0], ahi[ma][1], ahi[ma][2], ahi[ma][3],
                    a_base0 + abase + ma * 16 * SROW * 2);
            ldsm_x4(alo[ma][0], alo[ma][1], alo[ma][2], alo[ma][3],
                    a_base1 + abase + ma * 16 * SROW * 2);
        }
        uint32_t bhi[4][4], blo[4][4];
#pragma unroll
        for (int g = 0; g < 4; g++) {
            ldsm_x4(bhi[g][0], bhi[g][1], bhi[g][2], bhi[g][3],
                    b_base0 + abase + g * 16 * SROW * 2);
            ldsm_x4(blo[g][0], blo[g][1], blo[g][2], blo[g][3],
                    b_base1 + abase + g * 16 * SROW * 2);
        }

#pragma unroll
        for (int ma = 0; ma < 2; ma++)
#pragma unroll
            for (int g = 0; g < 4; g++)
#pragma unroll
                for (int h = 0; h < 2; h++) {
                    float* d = acc[ma][g * 2 + h];
                    mma_bf16(d, ahi[ma], &bhi[g][h * 2]);
                    mma_bf16(d, alo[ma], &bhi[g][h * 2]);
                    mma_bf16(d, ahi[ma], &blo[g][h * 2]);
                }

        CP_WAIT0();
        __syncthreads();
    }

    /* epilogue */
    int lg = lane >> 2, lt = lane & 3;
#pragma unroll
    for (int ma = 0; ma < 2; ma++) {
        int mrow0 = m0 + wm + ma * 16 + lg;
#pragma unroll
        for (int nb = 0; nb < 8; nb++) {
            int n = n0 + wn + nb * 8 + lt * 2;
            float* d = acc[ma][nb];
            if (mrow0 < M)
                *(float2*)(C + (size_t)mrow0 * N + n) = make_float2(d[0], d[1]);
            if (mrow0 + 8 < M)
                *(float2*)(C + (size_t)(mrow0 + 8) * N + n) = make_float2(d[2], d[3]);
        }
    }
}

/* ------------------------- attention coefficients ------------------------- */
template <int H, int C>
__global__ void attn_coef(const float* __restrict__ h,
                          const float* __restrict__ a_src,
                          const float* __restrict__ a_dst,
                          float* __restrict__ as, float* __restrict__ ad) {
    int gw = (blockIdx.x * blockDim.x + threadIdx.x) >> 5;
    int lane = threadIdx.x & 31;
    if (gw >= N_NODES * H) return;
    int n = gw / H, hh = gw % H;
    const float* hp = h + (size_t)n * (H * C) + hh * C;
    const float* sp = a_src + hh * C;
    const float* dp = a_dst + hh * C;
    float s = 0.f, d = 0.f;
#pragma unroll
    for (int c = lane; c < C; c += 32) {
        float v = hp[c];
        s += v * sp[c];
        d += v * dp[c];
    }
#pragma unroll
    for (int o = 16; o; o >>= 1) {
        s += __shfl_xor_sync(0xFFFFFFFFu, s, o);
        d += __shfl_xor_sync(0xFFFFFFFFu, d, o);
    }
    if (lane == 0) { as[gw] = s; ad[gw] = d; }
}

/* ------------------------- fused softmax + aggregate ------------------------- */
template <int H, int C, bool ELU, bool SPLIT>
__global__ __launch_bounds__(256)
void fused_agg(const float* __restrict__ as, const float* __restrict__ ad,
               const float* __restrict__ hfeat, const float* __restrict__ bias,
               float* __restrict__ alpha_out, float* __restrict__ aggout,
               __nv_bfloat16* __restrict__ ohi, __nv_bfloat16* __restrict__ olo) {
    int gw = (blockIdx.x * blockDim.x + threadIdx.x) >> 5;
    int lane = threadIdx.x & 31;
    if (gw >= N_NODES * H) return;
    int dst = gw / H, hh = gw % H;

    int beg = g_rowptr[dst], end = g_rowptr[dst + 1];
    float adv = ad[dst * H + hh];
    float* vb = g_vbuf + (size_t)hh * NE_TOT;

    /* pass 1: gather logits once, store contiguously, track max */
    float mx = -1e30f;
    for (int i = beg + lane; i < end; i += 32) {
        float v = as[g_esrc[i] * H + hh] + adv;
        v = v > 0.f ? v : 0.2f * v;
        vb[i] = v;
        mx = fmaxf(mx, v);
    }
#pragma unroll
    for (int o = 16; o; o >>= 1) mx = fmaxf(mx, __shfl_xor_sync(0xFFFFFFFFu, mx, o));

    /* pass 2: denom from contiguous buffer */
    float sm = 0.f;
    for (int i = beg + lane; i < end; i += 32) sm += __expf(vb[i] - mx);
#pragma unroll
    for (int o = 16; o; o >>= 1) sm += __shfl_xor_sync(0xFFFFFFFFu, sm, o);
    float inv = 1.f / sm;

    /* pass 3: alpha + gather-accumulate (software pipelined, depth 2) */
    constexpr int R = C / 128;
    float4 acc[R];
#pragma unroll
    for (int r = 0; r < R; r++) acc[r] = make_float4(0.f, 0.f, 0.f, 0.f);

    int i = beg;
    int s = g_esrc[i];
    int eo = g_eorig[i];
    float vv = vb[i];
    float4 tv[R];
    {
        const float4* hp = (const float4*)(hfeat + (size_t)s * (H * C) + hh * C);
#pragma unroll
        for (int r = 0; r < R; r++) tv[r] = hp[lane + 32 * r];
    }
    for (;;) {
        int inext = i + 1;
        bool more = inext < end;
        int s2 = 0, eo2 = 0;
        float vv2 = 0.f;
        float4 tv2[R];
        if (more) {
            s2 = g_esrc[inext];
            eo2 = g_eorig[inext];
            vv2 = vb[inext];
            const float4* hp2 = (const float4*)(hfeat + (size_t)s2 * (H * C) + hh * C);
#pragma unroll
            for (int r = 0; r < R; r++) tv2[r] = hp2[lane + 32 * r];
        }
        float a = __expf(vv - mx) * inv;
        if (lane == 0) alpha_out[eo * H + hh] = a;
#pragma unroll
        for (int r = 0; r < R; r++) {
            acc[r].x += a * tv[r].x;
            acc[r].y += a * tv[r].y;
            acc[r].z += a * tv[r].z;
            acc[r].w += a * tv[r].w;
        }
        if (!more) break;
        s = s2; eo = eo2; vv = vv2;
#pragma unroll
        for (int r = 0; r < R; r++) tv[r] = tv2[r];
        i = inext;
    }

    /* epilogue: bias (+ELU), fp32 out or bf16 hi/lo split */
#pragma unroll
    for (int r = 0; r < R; r++) {
        int c = (lane + 32 * r) * 4;
        const float* bp = bias + hh * C + c;
        float4 o = acc[r];
        o.x += bp[0]; o.y += bp[1]; o.z += bp[2]; o.w += bp[3];
        if (ELU) {
            o.x = o.x > 0.f ? o.x : expm1f(o.x);
            o.y = o.y > 0.f ? o.y : expm1f(o.y);
            o.z = o.z > 0.f ? o.z : expm1f(o.z);
            o.w = o.w > 0.f ? o.w : expm1f(o.w);
        }
        if (SPLIT) {
            size_t base = (size_t)dst * (H * C) + hh * C + c;
            float vv4[4] = { o.x, o.y, o.z, o.w };
#pragma unroll
            for (int q = 0; q < 4; q++) {
                __nv_bfloat16 h = __float2bfloat16(vv4[q]);
                ohi[base + q] = h;
                olo[base + q] = __float2bfloat16(vv4[q] - __bfloat162float(h));
            }
        } else {
            float* op = aggout + (size_t)dst * (H * C) + hh * C;
            ((float4*)op)[lane + 32 * r] = o;
        }
    }
}

/* ------------------------- launch ------------------------- */
extern "C" void kernel_launch(void* const* d_in, const int* in_sizes, int n_in,
                              void* d_out, int out_size) {
    const float* x      = (const float*)d_in[0];
    const int*   ei     = (const int*)  d_in[1];
    const float* W1     = (const float*)d_in[2];
    const float* a_src1 = (const float*)d_in[3];
    const float* a_dst1 = (const float*)d_in[4];
    const float* b1     = (const float*)d_in[5];
    const float* W2     = (const float*)d_in[6];
    const float* a_src2 = (const float*)d_in[7];
    const float* a_dst2 = (const float*)d_in[8];
    const float* b2     = (const float*)d_in[9];
    float* out = (float*)d_out;

    float *h1, *h2, *as1, *ad1, *as2, *ad2;
    __nv_bfloat16 *xhi, *xlo, *w1hi, *w1lo, *w2hi, *w2lo, *a1hi, *a1lo;
    cudaGetSymbolAddress((void**)&h1,   g_h1);
    cudaGetSymbolAddress((void**)&h2,   g_h2);
    cudaGetSymbolAddress((void**)&as1,  g_as1);
    cudaGetSymbolAddress((void**)&ad1,  g_ad1);
    cudaGetSymbolAddress((void**)&as2,  g_as2);
    cudaGetSymbolAddress((void**)&ad2,  g_ad2);
    cudaGetSymbolAddress((void**)&xhi,  g_xhi);
    cudaGetSymbolAddress((void**)&xlo,  g_xlo);
    cudaGetSymbolAddress((void**)&w1hi, g_w1hi);
    cudaGetSymbolAddress((void**)&w1lo, g_w1lo);
    cudaGetSymbolAddress((void**)&w2hi, g_w2hi);
    cudaGetSymbolAddress((void**)&w2lo, g_w2lo);
    cudaGetSymbolAddress((void**)&a1hi, g_a1hi);
    cudaGetSymbolAddress((void**)&a1lo, g_a1lo);

    /* 0-2: conversions (split_fp32_zero also zeroes CSR counters) */
    split_fp32_zero<<<(N_NODES * IN_CH + 255) / 256, 256>>>(x, xhi, xlo, N_NODES * IN_CH);
    split_w_t<<<(IN_CH * L1_F + 255) / 256, 256>>>(W1, w1hi, w1lo, IN_CH, L1_F);
    split_w_t<<<(L1_F * OUT_CH + 255) / 256, 256>>>(W2, w2hi, w2lo, L1_F, OUT_CH);

    /* 3-4: CSR counts + scan */
    count_deg<<<(NE_TOT + 255) / 256, 256>>>(ei);
    scan_rowptr<<<1, 1024>>>();

    /* 5: layer-1 GEMM (ncu capture slot) */
    gemm_hmma<<<dim3(L1_F / 128, 157), 256>>>(xhi, xlo, w1hi, w1lo, h1, N_NODES, L1_F);

    /* 6: finish CSR */
    scatter_edges<<<(NE_TOT + 255) / 256, 256>>>(ei);

    /* 7-8: layer-1 attention + aggregate */
    attn_coef<HEADS, HID><<<(N_NODES * HEADS + 7) / 8, 256>>>(h1, a_src1, a_dst1, as1, ad1);
    fused_agg<HEADS, HID, true, true><<<(N_NODES * HEADS + 7) / 8, 256>>>(
        as1, ad1, h1, b1, out + A1_OFF, nullptr, a1hi, a1lo);

    /* 9-11: layer 2 */
    gemm_hmma<<<dim3(OUT_CH / 128, 157), 256>>>(a1hi, a1lo, w2hi, w2lo, h2, N_NODES, OUT_CH);
    attn_coef<1, OUT_CH><<<(N_NODES + 7) / 8, 256>>>(h2, a_src2, a_dst2, as2, ad2);
    fused_agg<1, OUT_CH, false, false><<<(N_NODES + 7) / 8, 256>>>(
        as2, ad2, h2, b2, out + A2_OFF, out, nullptr, nullptr);
}